// round 7
// baseline (speedup 1.0000x reference)
#include <cuda_runtime.h>
#include <stdint.h>

// One CTA per batch row b.  B=4096, N=16384, F=16384 (derived at launch).
//  1) stage row (F floats = 64KB) into dynamic smem, coalesced float4 loads
//  2) pass 1: gather pref from smem, scale by weight, accumulate row sum
//  3) block reduce -> mean
//  4) pass 2: re-gather, scale, relu(v - 0.1*mean), coalesced float4 stores
// Two-pass recompute keeps regs ~32 so 3 CTAs/SM (smem-limited) with no spills.

#define THREADS 512
#define MEAN_SUB 0.1f

__global__ __launch_bounds__(THREADS, 3)
void sensory_kernel(const float* __restrict__ enc,
                    const float* __restrict__ wts,
                    const int*   __restrict__ pref,
                    float* __restrict__ out,
                    int N, int F, unsigned fmask, int use_mask)
{
    extern __shared__ float row[];
    const int tid = threadIdx.x;
    const int b   = blockIdx.x;

    // ---- stage row into smem, float4 coalesced ----
    {
        const float4* e4 = reinterpret_cast<const float4*>(enc + (size_t)b * F);
        float4* r4 = reinterpret_cast<float4*>(row);
        const int n4 = F >> 2;
        #pragma unroll 4
        for (int i = tid; i < n4; i += THREADS) r4[i] = e4[i];
    }
    __syncthreads();

    const int iters = N / (THREADS * 4);       // 8 for this problem
    const int4*   p4 = reinterpret_cast<const int4*>(pref);
    const float4* w4 = reinterpret_cast<const float4*>(wts);

    // ---- pass 1: gather + scale, sum only ----
    float sum = 0.0f;
    for (int it = 0; it < iters; ++it) {
        const int vi = it * THREADS + tid;
        int4   p = p4[vi];
        float4 w = w4[vi];
        int ix, iy, iz, iw;
        if (use_mask) {
            ix = p.x & (int)fmask; iy = p.y & (int)fmask;
            iz = p.z & (int)fmask; iw = p.w & (int)fmask;
        } else {
            ix = ((unsigned)p.x) % (unsigned)F; iy = ((unsigned)p.y) % (unsigned)F;
            iz = ((unsigned)p.z) % (unsigned)F; iw = ((unsigned)p.w) % (unsigned)F;
        }
        sum += (row[ix] * w.x + row[iy] * w.y)
             + (row[iz] * w.z + row[iw] * w.w);
    }

    // ---- block reduction ----
    __shared__ float wsums[THREADS / 32];
    #pragma unroll
    for (int o = 16; o > 0; o >>= 1)
        sum += __shfl_xor_sync(0xFFFFFFFFu, sum, o);
    if ((tid & 31) == 0) wsums[tid >> 5] = sum;
    __syncthreads();

    float tot = 0.0f;
    #pragma unroll
    for (int i = 0; i < THREADS / 32; ++i) tot += wsums[i];

    const float ms = MEAN_SUB * tot / (float)N;

    // ---- pass 2: re-gather, scale, subtract, relu, store ----
    float4* o4 = reinterpret_cast<float4*>(out + (size_t)b * N);
    for (int it = 0; it < iters; ++it) {
        const int vi = it * THREADS + tid;
        int4   p = p4[vi];
        float4 w = w4[vi];
        int ix, iy, iz, iw;
        if (use_mask) {
            ix = p.x & (int)fmask; iy = p.y & (int)fmask;
            iz = p.z & (int)fmask; iw = p.w & (int)fmask;
        } else {
            ix = ((unsigned)p.x) % (unsigned)F; iy = ((unsigned)p.y) % (unsigned)F;
            iz = ((unsigned)p.z) % (unsigned)F; iw = ((unsigned)p.w) % (unsigned)F;
        }
        float4 v;
        v.x = fmaxf(row[ix] * w.x - ms, 0.0f);
        v.y = fmaxf(row[iy] * w.y - ms, 0.0f);
        v.z = fmaxf(row[iz] * w.z - ms, 0.0f);
        v.w = fmaxf(row[iw] * w.w - ms, 0.0f);
        o4[vi] = v;
    }
}

extern "C" void kernel_launch(void* const* d_in, const int* in_sizes, int n_in,
                              void* d_out, int out_size)
{
    const float* enc  = (const float*)d_in[0];   // [B, F]
    const float* wts  = (const float*)d_in[1];   // [N]
    const int*   pref = (const int*)d_in[2];     // [N]
    float* out = (float*)d_out;                  // [B, N]

    const int N = in_sizes[1];
    const int B = out_size / N;
    const int F = in_sizes[0] / B;

    const int use_mask = ((F & (F - 1)) == 0) ? 1 : 0;
    const unsigned fmask = (unsigned)(F - 1);

    const size_t smem = (size_t)F * sizeof(float);
    cudaFuncSetAttribute(sensory_kernel,
                         cudaFuncAttributeMaxDynamicSharedMemorySize,
                         (int)smem);

    sensory_kernel<<<B, THREADS, smem>>>(enc, wts, pref, out, N, F, fmask, use_mask);
}

// round 12
// speedup vs baseline: 1.2956x; 1.2956x over previous
#include <cuda_runtime.h>
#include <stdint.h>

// B=4096, N=16384, F=16384 (derived at launch; F capped at MAXF).
//
// Launch 1: zero c[]            (device-global scratch, no allocation)
// Launch 2: c[f] += w[n] for f = pref[n] % F   (atomic scatter, 16K ops)
// Launch 3: one CTA per row:
//   - stage row into smem (float4, coalesced) WHILE accumulating
//     dot(row, c) in the same loop (c streams coalesced, L2-resident)
//     => mean_b = dot(row, c) / N  without any gather
//   - block reduce -> mean; ms = 0.1*mean
//   - single gather pass: out = relu(row[pref]*w - ms), float4 stores
//
// Removes one of the two random-gather passes (R7 bottleneck: L1=89%,
// DRAM=30%).

#define THREADS 512
#define MEAN_SUB 0.1f
#define MAXF 65536

__device__ float g_c[MAXF];

__global__ void zero_c_kernel(void)
{
    int i = blockIdx.x * blockDim.x + threadIdx.x;
    if (i < MAXF) g_c[i] = 0.0f;
}

__global__ void scatter_c_kernel(const float* __restrict__ wts,
                                 const int*   __restrict__ pref,
                                 int N, int F, unsigned fmask, int use_mask)
{
    int n = blockIdx.x * blockDim.x + threadIdx.x;
    if (n < N) {
        int f = use_mask ? (pref[n] & (int)fmask)
                         : (int)(((unsigned)pref[n]) % (unsigned)F);
        atomicAdd(&g_c[f], wts[n]);
    }
}

__global__ __launch_bounds__(THREADS, 3)
void sensory_kernel(const float* __restrict__ enc,
                    const float* __restrict__ wts,
                    const int*   __restrict__ pref,
                    float* __restrict__ out,
                    int N, int F, unsigned fmask, int use_mask)
{
    extern __shared__ float row[];
    const int tid = threadIdx.x;
    const int b   = blockIdx.x;

    // ---- stage row into smem + fused dot(row, c) ----
    float partial = 0.0f;
    {
        const float4* e4 = reinterpret_cast<const float4*>(enc + (size_t)b * F);
        const float4* c4 = reinterpret_cast<const float4*>(g_c);
        float4* r4 = reinterpret_cast<float4*>(row);
        const int n4 = F >> 2;
        #pragma unroll 4
        for (int i = tid; i < n4; i += THREADS) {
            float4 e = e4[i];
            r4[i] = e;
            float4 c = __ldg(&c4[i]);
            partial += (e.x * c.x + e.y * c.y) + (e.z * c.z + e.w * c.w);
        }
    }

    // ---- block reduction of partial dot ----
    __shared__ float wsums[THREADS / 32];
    #pragma unroll
    for (int o = 16; o > 0; o >>= 1)
        partial += __shfl_xor_sync(0xFFFFFFFFu, partial, o);
    if ((tid & 31) == 0) wsums[tid >> 5] = partial;
    __syncthreads();   // also orders the smem row staging for the gather below

    float tot = 0.0f;
    #pragma unroll
    for (int i = 0; i < THREADS / 32; ++i) tot += wsums[i];

    const float ms = MEAN_SUB * tot / (float)N;

    // ---- single gather pass: scale, subtract, relu, store ----
    const int iters = N / (THREADS * 4);       // 8 for this problem
    const int4*   p4 = reinterpret_cast<const int4*>(pref);
    const float4* w4 = reinterpret_cast<const float4*>(wts);
    float4* o4 = reinterpret_cast<float4*>(out + (size_t)b * N);

    for (int it = 0; it < iters; ++it) {
        const int vi = it * THREADS + tid;
        int4   p = __ldg(&p4[vi]);
        float4 w = __ldg(&w4[vi]);
        int ix, iy, iz, iw;
        if (use_mask) {
            ix = p.x & (int)fmask; iy = p.y & (int)fmask;
            iz = p.z & (int)fmask; iw = p.w & (int)fmask;
        } else {
            ix = ((unsigned)p.x) % (unsigned)F; iy = ((unsigned)p.y) % (unsigned)F;
            iz = ((unsigned)p.z) % (unsigned)F; iw = ((unsigned)p.w) % (unsigned)F;
        }
        float4 v;
        v.x = fmaxf(row[ix] * w.x - ms, 0.0f);
        v.y = fmaxf(row[iy] * w.y - ms, 0.0f);
        v.z = fmaxf(row[iz] * w.z - ms, 0.0f);
        v.w = fmaxf(row[iw] * w.w - ms, 0.0f);
        o4[vi] = v;
    }
}

extern "C" void kernel_launch(void* const* d_in, const int* in_sizes, int n_in,
                              void* d_out, int out_size)
{
    const float* enc  = (const float*)d_in[0];   // [B, F]
    const float* wts  = (const float*)d_in[1];   // [N]
    const int*   pref = (const int*)d_in[2];     // [N]
    float* out = (float*)d_out;                  // [B, N]

    const int N = in_sizes[1];
    const int B = out_size / N;
    const int F = in_sizes[0] / B;

    const int use_mask = ((F & (F - 1)) == 0) ? 1 : 0;
    const unsigned fmask = (unsigned)(F - 1);

    // 1) zero the per-feature weight histogram (full extent, deterministic)
    zero_c_kernel<<<(MAXF + 255) / 256, 256>>>();
    // 2) scatter weights by preferred feature
    scatter_c_kernel<<<(N + 255) / 256, 256>>>(wts, pref, N, F, fmask, use_mask);

    // 3) main fused kernel
    const size_t smem = (size_t)F * sizeof(float);
    cudaFuncSetAttribute(sensory_kernel,
                         cudaFuncAttributeMaxDynamicSharedMemorySize,
                         (int)smem);
    sensory_kernel<<<B, THREADS, smem>>>(enc, wts, pref, out, N, F, fmask, use_mask);
}

// round 14
// speedup vs baseline: 1.6700x; 1.2889x over previous
#include <cuda_runtime.h>
#include <stdint.h>

// B=4096, N=16384, F=16384 (derived at launch).
//
// Launch 1: zero c[0..F)                       (device-global scratch)
// Launch 2: c[f] += w[n], f = pref[n] % F      (atomic scatter)
// Launch 3: one CTA per PAIR of rows (b0, b1=b0+1):
//   - stage both rows INTERLEAVED in smem: srow[f] = {row0[f], row1[f]}
//     (float2 global loads, conflict-free float4 STS), fused with
//     dot(row0,c) and dot(row1,c) for the two means
//   - one LDS.64 per neuron serves BOTH rows (gather cost amortized 2x,
//     index/weight loads amortized 2x)
//   - out[bi][n] = relu(g_i * w[n] - 0.1*mean_i), float4 coalesced stores
//
// R7/R12 evidence: L1TEX wavefront pipe is the bottleneck (L1=89%/~60%,
// DRAM ~30%). This cuts per-row L1 work ~30%.

#define THREADS 1024
#define MEAN_SUB 0.1f
#define MAXF 65536

__device__ float g_c[MAXF];

__global__ void zero_c_kernel(int F)
{
    int i = blockIdx.x * blockDim.x + threadIdx.x;
    if (i < F) g_c[i] = 0.0f;
}

__global__ void scatter_c_kernel(const float* __restrict__ wts,
                                 const int*   __restrict__ pref,
                                 int N, int F, unsigned fmask, int use_mask)
{
    int n = blockIdx.x * blockDim.x + threadIdx.x;
    if (n < N) {
        int f = use_mask ? (pref[n] & (int)fmask)
                         : (int)(((unsigned)pref[n]) % (unsigned)F);
        atomicAdd(&g_c[f], wts[n]);
    }
}

__global__ __launch_bounds__(THREADS, 1)
void sensory_pair_kernel(const float* __restrict__ enc,
                         const float* __restrict__ wts,
                         const int*   __restrict__ pref,
                         float* __restrict__ out,
                         int N, int F, unsigned fmask, int use_mask, int B)
{
    extern __shared__ float2 srow[];   // srow[f] = {row0[f], row1[f]}
    const int tid = threadIdx.x;
    const int b0  = blockIdx.x * 2;
    int b1 = b0 + 1;
    const int have2 = (b1 < B);
    if (!have2) b1 = b0;               // duplicate row; second store skipped

    // ---- stage both rows interleaved + fused dots with c ----
    float s0 = 0.0f, s1 = 0.0f;
    {
        const float2* e0 = reinterpret_cast<const float2*>(enc + (size_t)b0 * F);
        const float2* e1 = reinterpret_cast<const float2*>(enc + (size_t)b1 * F);
        const float2* c2 = reinterpret_cast<const float2*>(g_c);
        float4* s4 = reinterpret_cast<float4*>(srow);
        const int n2 = F >> 1;         // feature pairs
        #pragma unroll 4
        for (int i = tid; i < n2; i += THREADS) {
            float2 a = e0[i];
            float2 d = e1[i];
            float2 c = __ldg(&c2[i]);
            // srow[2i] = {a.x, d.x}; srow[2i+1] = {a.y, d.y}  as one float4
            float4 v; v.x = a.x; v.y = d.x; v.z = a.y; v.w = d.y;
            s4[i] = v;
            s0 += a.x * c.x + a.y * c.y;
            s1 += d.x * c.x + d.y * c.y;
        }
    }

    // ---- block reduction of both partial dots ----
    __shared__ float r0s[THREADS / 32];
    __shared__ float r1s[THREADS / 32];
    #pragma unroll
    for (int o = 16; o > 0; o >>= 1) {
        s0 += __shfl_xor_sync(0xFFFFFFFFu, s0, o);
        s1 += __shfl_xor_sync(0xFFFFFFFFu, s1, o);
    }
    if ((tid & 31) == 0) { r0s[tid >> 5] = s0; r1s[tid >> 5] = s1; }
    __syncthreads();   // also publishes the staged smem rows

    float t0 = 0.0f, t1 = 0.0f;
    #pragma unroll
    for (int i = 0; i < THREADS / 32; ++i) { t0 += r0s[i]; t1 += r1s[i]; }

    const float ms0 = MEAN_SUB * t0 / (float)N;
    const float ms1 = MEAN_SUB * t1 / (float)N;

    // ---- single gather pass, one LDS.64 serves both rows ----
    const int iters = N / (THREADS * 4);       // 4 for this problem
    const int4*   p4 = reinterpret_cast<const int4*>(pref);
    const float4* w4 = reinterpret_cast<const float4*>(wts);
    float4* o0 = reinterpret_cast<float4*>(out + (size_t)b0 * N);
    float4* o1 = reinterpret_cast<float4*>(out + (size_t)b1 * N);

    for (int it = 0; it < iters; ++it) {
        const int vi = it * THREADS + tid;
        int4   p = __ldg(&p4[vi]);
        float4 w = __ldg(&w4[vi]);
        int ix, iy, iz, iw;
        if (use_mask) {
            ix = p.x & (int)fmask; iy = p.y & (int)fmask;
            iz = p.z & (int)fmask; iw = p.w & (int)fmask;
        } else {
            ix = ((unsigned)p.x) % (unsigned)F; iy = ((unsigned)p.y) % (unsigned)F;
            iz = ((unsigned)p.z) % (unsigned)F; iw = ((unsigned)p.w) % (unsigned)F;
        }
        float2 gx = srow[ix];
        float2 gy = srow[iy];
        float2 gz = srow[iz];
        float2 gw = srow[iw];

        float4 v0;
        v0.x = fmaxf(gx.x * w.x - ms0, 0.0f);
        v0.y = fmaxf(gy.x * w.y - ms0, 0.0f);
        v0.z = fmaxf(gz.x * w.z - ms0, 0.0f);
        v0.w = fmaxf(gw.x * w.w - ms0, 0.0f);
        o0[vi] = v0;

        if (have2) {
            float4 v1;
            v1.x = fmaxf(gx.y * w.x - ms1, 0.0f);
            v1.y = fmaxf(gy.y * w.y - ms1, 0.0f);
            v1.z = fmaxf(gz.y * w.z - ms1, 0.0f);
            v1.w = fmaxf(gw.y * w.w - ms1, 0.0f);
            o1[vi] = v1;
        }
    }
}

extern "C" void kernel_launch(void* const* d_in, const int* in_sizes, int n_in,
                              void* d_out, int out_size)
{
    const float* enc  = (const float*)d_in[0];   // [B, F]
    const float* wts  = (const float*)d_in[1];   // [N]
    const int*   pref = (const int*)d_in[2];     // [N]
    float* out = (float*)d_out;                  // [B, N]

    const int N = in_sizes[1];
    const int B = out_size / N;
    const int F = in_sizes[0] / B;

    const int use_mask = ((F & (F - 1)) == 0) ? 1 : 0;
    const unsigned fmask = (unsigned)(F - 1);

    // 1) zero the per-feature weight histogram
    zero_c_kernel<<<(F + 255) / 256, 256>>>(F);
    // 2) scatter weights by preferred feature
    scatter_c_kernel<<<(N + 255) / 256, 256>>>(wts, pref, N, F, fmask, use_mask);

    // 3) main fused kernel: one CTA per row pair, interleaved smem
    const size_t smem = 2 * (size_t)F * sizeof(float);   // 128 KB for F=16384
    cudaFuncSetAttribute(sensory_pair_kernel,
                         cudaFuncAttributeMaxDynamicSharedMemorySize,
                         (int)smem);
    const int grid = (B + 1) / 2;
    sensory_pair_kernel<<<grid, THREADS, smem>>>(enc, wts, pref, out,
                                                 N, F, fmask, use_mask, B);
}